// round 9
// baseline (speedup 1.0000x reference)
#include <cuda_runtime.h>

// Problem constants (B=4, N_obj=8 -> 32 objects, N_v=2048 points, 64 anchors, 16-NN)
#define N_V        2048
#define N_OBJS     32
#define ANCHORS    64
#define KNN        16
#define FPS_THREADS 256
#define PPT        8            // points per thread in FPS (2048/256)
#define FULL       0xffffffffu

// per-anchor pack: (qx, qy, qz, bitcast(anchor_index))
__device__ float4 g_qpack[N_OBJS * ANCHORS];

// ---------------------------------------------------------------------------
// Kernel 1: farthest point sampling, one block per object (R2-proven body).
// NEW: tail writes the per-anchor query pack AND output fields o[3..11]
// (velocity / rel-pos / physics gathers depend only on anchor indices).
// ---------------------------------------------------------------------------
__global__ __launch_bounds__(FPS_THREADS) void fps_kernel(const float* __restrict__ pos,
                                                          const float* __restrict__ vel,
                                                          const float* __restrict__ phys,
                                                          const float* __restrict__ refp,
                                                          float* __restrict__ out) {
    const int o = blockIdx.x;
    const float* __restrict__ P = pos + (size_t)o * N_V * 3;

    __shared__ float spts[N_V * 3];                       // 24 KB
    __shared__ unsigned long long swk[2][FPS_THREADS / 32];
    __shared__ int sanch[ANCHORS];

    const int tid  = threadIdx.x;
    const int lane = tid & 31;
    const int wid  = tid >> 5;

    for (int i = tid; i < N_V * 3; i += FPS_THREADS) spts[i] = P[i];
    __syncthreads();

    float px[PPT], py[PPT], pz[PPT], md[PPT];
    const float x0 = spts[0], y0 = spts[1], z0 = spts[2];
#pragma unroll
    for (int k = 0; k < PPT; k++) {
        const int j = tid + FPS_THREADS * k;
        px[k] = spts[j * 3 + 0];
        py[k] = spts[j * 3 + 1];
        pz[k] = spts[j * 3 + 2];
        const float dx = px[k] - x0, dy = py[k] - y0, dz = pz[k] - z0;
        md[k] = dx * dx + dy * dy + dz * dz;              // matches reference FPS formula
    }
    if (tid == 0) sanch[0] = 0;

    int buf = 0;
    for (int it = 1; it < ANCHORS; ++it) {
        // local argmax over my 8 points
        float bv = md[0];
        int   bi = tid;
#pragma unroll
        for (int k = 1; k < PPT; k++) {
            if (md[k] > bv) { bv = md[k]; bi = tid + FPS_THREADS * k; }
        }
        // warp argmax: md >= 0 so raw float bits are monotonic as unsigned
        const unsigned u = __float_as_uint(bv);
        const unsigned m = __reduce_max_sync(FULL, u);
        const unsigned bal = __ballot_sync(FULL, u == m);
        const int src = __ffs(bal) - 1;
        const int ci  = __shfl_sync(FULL, bi, src);
        if (lane == 0)
            swk[buf][wid] = ((unsigned long long)m << 32) | (unsigned)(0x7FFFFFFF - ci);
        __syncthreads();

        // every thread reduces the 8 warp partials (no second barrier needed)
        unsigned long long best = swk[buf][0];
#pragma unroll
        for (int w = 1; w < FPS_THREADS / 32; w++) {
            const unsigned long long c = swk[buf][w];
            if (c > best) best = c;
        }
        const int bidx = 0x7FFFFFFF - (int)(unsigned)(best & 0xFFFFFFFFull);
        if (tid == 0) sanch[it] = bidx;

        const float qx = spts[bidx * 3 + 0];
        const float qy = spts[bidx * 3 + 1];
        const float qz = spts[bidx * 3 + 2];
#pragma unroll
        for (int k = 0; k < PPT; k++) {
            const float dx = px[k] - qx, dy = py[k] - qy, dz = pz[k] - qz;
            const float d = dx * dx + dy * dy + dz * dz;
            md[k] = fminf(md[k], d);
        }
        buf ^= 1;
    }
    __syncthreads();                                      // sanch complete

    // ---- tail: anchor pack + output fields o[3..11] (64 parallel threads) ----
    if (tid < ANCHORS) {
        const int a    = o * ANCHORS + tid;
        const int aidx = sanch[tid];
        const float qx = spts[aidx * 3 + 0];
        const float qy = spts[aidx * 3 + 1];
        const float qz = spts[aidx * 3 + 2];
        g_qpack[a] = make_float4(qx, qy, qz, __int_as_float(aidx));

        float* __restrict__ op = out + (size_t)a * 12;
        const float* __restrict__ V = vel  + (size_t)o * N_V * 3;
        const float* __restrict__ R = refp + (size_t)o * N_V * 3;
        // anchor_vel
        op[3] = V[aidx * 3 + 0];
        op[4] = V[aidx * 3 + 1];
        op[5] = V[aidx * 3 + 2];
        // anchor_rel = pos - ref
        op[6] = qx - R[aidx * 3 + 0];
        op[7] = qy - R[aidx * 3 + 1];
        op[8] = qz - R[aidx * 3 + 2];
        // physics broadcast
        op[9]  = phys[o * 3 + 0];
        op[10] = phys[o * 3 + 1];
        op[11] = phys[o * 3 + 2];
    }
}

// monotonic total-order key for floats (handles tiny negative d2 from cancellation)
__device__ __forceinline__ unsigned fkey(float f) {
    const unsigned u = __float_as_uint(f);
    return (u & 0x80000000u) ? ~u : (u | 0x80000000u);
}

// ---------------------------------------------------------------------------
// Kernel 2: KNN at anchors + mean-offset output (o[0..2] only).
// One BLOCK (4 warps) per anchor; lane owns 16 CONTIGUOUS points loaded as
// 12 x LDG.128 in 4-point chunks (low live-register pressure). Prologue is
// a single LDG.128 of the fps-produced query pack (no dependent chain).
// Selection = R4's measured-best: lane bitonic-sorts its 16 distances,
// warp pop-min extracts its 16 smallest (ballot-selected winner, register
// shift), warp 0 merges the 64 candidates to threshold T, threads
// accumulate positions with d <= T. Distances parked in SMEM.
// Distance arithmetic bit-identical to the R2 kernel (4.7e-8).
// ---------------------------------------------------------------------------
__global__ __launch_bounds__(128, 8) void knn_kernel(const float* __restrict__ pos,
                                                     float* __restrict__ out) {
    __shared__ float dsh[KNN][128];                       // 8 KB distance park
    __shared__ float cand[4 * KNN];
    __shared__ float sT;
    __shared__ float psum[4][3];

    const int a    = blockIdx.x;                 // global anchor id [0, 2048)
    const int tid  = threadIdx.x;
    const int lane = tid & 31;
    const int wid  = tid >> 5;
    const int obj  = a >> 6;

    const float4 qp = g_qpack[a];                // single 16B load: q + aidx
    const float qx = qp.x, qy = qp.y, qz = qp.z;
    const int aidx = __float_as_int(qp.w);
    const float sqq = qx * qx + qy * qy + qz * qz;

    const float* __restrict__ P = pos + (size_t)obj * N_V * 3;
    const int pbase = (wid << 9) + (lane << 4);  // my 16 contiguous points
    const float4* __restrict__ Pw = (const float4*)(P + (size_t)pbase * 3);

    // ---- distances, 4 points per 3-float4 chunk (expression identical R2) ----
    float v[KNN];
#pragma unroll
    for (int c = 0; c < 4; c++) {
        const float4 A = Pw[3 * c], B = Pw[3 * c + 1], C = Pw[3 * c + 2];
        const float xs[4] = {A.x, A.w, B.z, C.y};
        const float ys[4] = {A.y, B.x, B.w, C.z};
        const float zs[4] = {A.z, B.y, C.x, C.w};
#pragma unroll
        for (int t = 0; t < 4; t++) {
            const int k = 4 * c + t;
            const float x = xs[t], y = ys[t], z = zs[t];
            float dd = (x * x + y * y + z * z + sqq) - 2.0f * (x * qx + y * qy + z * qz);
            if (pbase + k == aidx) dd += 1e10f;  // reference's diagonal exclusion
            v[k] = dd;
            dsh[k][tid] = dd;
        }
    }

    // ---- bitonic sort of the 16 values (ascending), value-only ----
#pragma unroll
    for (int kk = 2; kk <= KNN; kk <<= 1) {
#pragma unroll
        for (int jj = kk >> 1; jj > 0; jj >>= 1) {
#pragma unroll
            for (int i = 0; i < KNN; i++) {
                const int l = i ^ jj;
                if (l > i) {
                    const float va = v[i], vb = v[l];
                    const float lo = fminf(va, vb), hi = fmaxf(va, vb);
                    const bool up = ((i & kk) == 0);
                    v[i] = up ? lo : hi;
                    v[l] = up ? hi : lo;
                }
            }
        }
    }

    // ---- per-warp pop-min extraction: 16 smallest of this warp's 512 ----
    const float FINF = __int_as_float(0x7f800000);
#pragma unroll
    for (int r = 0; r < KNN; r++) {
        const unsigned key = fkey(v[0]);
        const unsigned km  = __reduce_min_sync(FULL, key);
        const unsigned bal = __ballot_sync(FULL, key == km);
        const int win = __ffs(bal) - 1;
        if (lane == win) {
            cand[(wid << 4) + r] = v[0];
#pragma unroll
            for (int t = 0; t < KNN - 1; t++) v[t] = v[t + 1];
            v[KNN - 1] = FINF;
        }
    }
    __syncthreads();

    // ---- warp 0: T = 16th smallest of the 64 candidates (runs sorted) ----
    if (wid == 0) {
        float c0 = cand[lane * 2], c1 = cand[lane * 2 + 1];
        float T = 0.0f;
#pragma unroll
        for (int r = 0; r < KNN; r++) {
            const unsigned key = fkey(c0);
            const unsigned km  = __reduce_min_sync(FULL, key);
            const unsigned bal = __ballot_sync(FULL, key == km);
            const int win = __ffs(bal) - 1;
            T = __shfl_sync(FULL, c0, win);
            if (lane == win) { c0 = c1; c1 = FINF; }
        }
        if (lane == 0) sT = T;
    }
    __syncthreads();
    const float T = sT;

    // ---- accumulate positions of the 16 selected points (float4 reload) ----
    float sx = 0.f, sy = 0.f, sz = 0.f;
#pragma unroll
    for (int c = 0; c < 4; c++) {
        const float4 A = Pw[3 * c], B = Pw[3 * c + 1], C = Pw[3 * c + 2];
        const float xs[4] = {A.x, A.w, B.z, C.y};
        const float ys[4] = {A.y, B.x, B.w, C.z};
        const float zs[4] = {A.z, B.y, C.x, C.w};
#pragma unroll
        for (int t = 0; t < 4; t++) {
            const int k = 4 * c + t;
            if (dsh[k][tid] <= T) { sx += xs[t]; sy += ys[t]; sz += zs[t]; }
        }
    }
#pragma unroll
    for (int off = 16; off; off >>= 1) {
        sx += __shfl_xor_sync(FULL, sx, off);
        sy += __shfl_xor_sync(FULL, sy, off);
        sz += __shfl_xor_sync(FULL, sz, off);
    }
    if (lane == 0) { psum[wid][0] = sx; psum[wid][1] = sy; psum[wid][2] = sz; }
    __syncthreads();

    if (tid == 0) {
        const float nx = psum[0][0] + psum[1][0] + psum[2][0] + psum[3][0];
        const float ny = psum[0][1] + psum[1][1] + psum[2][1] + psum[3][1];
        const float nz = psum[0][2] + psum[1][2] + psum[2][2] + psum[3][2];
        float* __restrict__ o = out + (size_t)a * 12;
        const float inv = 1.0f / 16.0f;
        o[0] = nx * inv - qx;                    // anchor_dist: mean(neigh) - p
        o[1] = ny * inv - qy;
        o[2] = nz * inv - qz;
    }
}

extern "C" void kernel_launch(void* const* d_in, const int* in_sizes, int n_in,
                              void* d_out, int out_size) {
    const float* positions  = (const float*)d_in[0];
    const float* velocities = (const float*)d_in[1];
    const float* physics    = (const float*)d_in[2];
    const float* refpos     = (const float*)d_in[3];
    float* out = (float*)d_out;

    fps_kernel<<<N_OBJS, FPS_THREADS>>>(positions, velocities, physics, refpos, out);
    knn_kernel<<<N_OBJS * ANCHORS, 128>>>(positions, out);
}